// round 4
// baseline (speedup 1.0000x reference)
#include <cuda_runtime.h>
#include <cuda_bf16.h>
#include <cfloat>
#include <math.h>

#define BS 16
#define CAP 64
#define VOCAB 50265
#define TOPK 5
#define SEQ 256
#define AT 32
#define D 768
#define END_ID 2

// Scratch (allocation-free rule: __device__ globals)
__device__ float g_sce[BS * CAP * D];   // 3.1 MB
__device__ float g_att[BS * AT * D];    // 1.5 MB

// ---------------------------------------------------------------------------
// Kernel 1: per-(b,c) top-5 over vocab -> softmax -> weighted embed gather
// ---------------------------------------------------------------------------
__device__ __forceinline__ void tk_insert(float v, int idx, float lv[5], int li[5]) {
    if (v <= lv[4]) return;
    if (v > lv[2]) {
        if (v > lv[1]) {
            if (v > lv[0]) {
                lv[4]=lv[3]; li[4]=li[3]; lv[3]=lv[2]; li[3]=li[2];
                lv[2]=lv[1]; li[2]=li[1]; lv[1]=lv[0]; li[1]=li[0];
                lv[0]=v; li[0]=idx;
            } else {
                lv[4]=lv[3]; li[4]=li[3]; lv[3]=lv[2]; li[3]=li[2];
                lv[2]=lv[1]; li[2]=li[1]; lv[1]=v; li[1]=idx;
            }
        } else {
            lv[4]=lv[3]; li[4]=li[3]; lv[3]=lv[2]; li[3]=li[2];
            lv[2]=v; li[2]=idx;
        }
    } else {
        if (v > lv[3]) {
            lv[4]=lv[3]; li[4]=li[3]; lv[3]=v; li[3]=idx;
        } else {
            lv[4]=v; li[4]=idx;
        }
    }
}

__global__ __launch_bounds__(256, 4)
void topk_sce_kernel(const float* __restrict__ cap_out,
                     const float* __restrict__ emb,
                     float* __restrict__ sce) {
    const int row = blockIdx.x;            // b*CAP + c
    const int t   = threadIdx.x;
    const float* base = cap_out + (size_t)row * VOCAB;

    float lv[5] = {-FLT_MAX, -FLT_MAX, -FLT_MAX, -FLT_MAX, -FLT_MAX};
    int   li[5] = {0x7fffffff, 0x7fffffff, 0x7fffffff, 0x7fffffff, 0x7fffffff};

    // Alignment fix: row base may be only 4B-aligned (VOCAB odd-ish)
    const int mis = (int)(((size_t)base >> 2) & 3);     // floats to 16B boundary
    const int pre = (4 - mis) & 3;
    if (t < pre) tk_insert(base[t], t, lv, li);

    const int n4 = (VOCAB - pre) >> 2;
    const float4* v4 = (const float4*)(base + pre);
    for (int i = t; i < n4; i += 256) {
        float4 x = __ldcs(v4 + i);
        int idx = pre + (i << 2);
        tk_insert(x.x, idx,     lv, li);
        tk_insert(x.y, idx + 1, lv, li);
        tk_insert(x.z, idx + 2, lv, li);
        tk_insert(x.w, idx + 3, lv, li);
    }
    const int done = pre + (n4 << 2);
    if (t < VOCAB - done) tk_insert(base[done + t], done + t, lv, li);

    // Block-wide selection of global top-5: 5 rounds of tree argmax
    __shared__ float sv[256];
    __shared__ int   si[256];
    __shared__ float topv[TOPK];
    __shared__ int   topid[TOPK];
    int ptr = 0;
    for (int r = 0; r < TOPK; r++) {
        sv[t] = (ptr < 5) ? lv[ptr] : -FLT_MAX;
        si[t] = (ptr < 5) ? li[ptr] : 0x7fffffff;
        __syncthreads();
        #pragma unroll
        for (int s = 128; s > 0; s >>= 1) {
            if (t < s) {
                float ov = sv[t + s]; int oi = si[t + s];
                if (ov > sv[t] || (ov == sv[t] && oi < si[t])) { sv[t] = ov; si[t] = oi; }
            }
            __syncthreads();
        }
        if (t == 0) { topv[r] = sv[0]; topid[r] = si[0]; }
        int win = si[0];
        if (ptr < 5 && li[ptr] == win) ptr++;
        __syncthreads();
    }

    // Softmax over 5 (descending -> topv[0] is max)
    __shared__ float w[TOPK];
    if (t == 0) {
        float m = topv[0];
        float e0 = expf(topv[0] - m), e1 = expf(topv[1] - m), e2 = expf(topv[2] - m);
        float e3 = expf(topv[3] - m), e4 = expf(topv[4] - m);
        float inv = 1.0f / (e0 + e1 + e2 + e3 + e4);
        w[0]=e0*inv; w[1]=e1*inv; w[2]=e2*inv; w[3]=e3*inv; w[4]=e4*inv;
    }
    __syncthreads();

    const float* e0 = emb + (size_t)topid[0] * D;
    const float* e1 = emb + (size_t)topid[1] * D;
    const float* e2 = emb + (size_t)topid[2] * D;
    const float* e3 = emb + (size_t)topid[3] * D;
    const float* e4 = emb + (size_t)topid[4] * D;
    float w0 = w[0], w1 = w[1], w2 = w[2], w3 = w[3], w4 = w[4];
    float* srow = sce + (size_t)row * D;
    #pragma unroll
    for (int d = t; d < D; d += 256) {
        srow[d] = w0*__ldg(e0+d) + w1*__ldg(e1+d) + w2*__ldg(e2+d)
                + w3*__ldg(e3+d) + w4*__ldg(e4+d);
    }
}

// ---------------------------------------------------------------------------
// Kernel 2: attention  (block = (qtile of 4, b)), 256 threads
// ---------------------------------------------------------------------------
__global__ __launch_bounds__(256, 4)
void attn_kernel(const float* __restrict__ qin,     // [BS, AT, D]
                 const float* __restrict__ sce,     // [BS, CAP, D]
                 const int*   __restrict__ clen,    // [BS]
                 float*       __restrict__ att) {   // [BS, AT, D]
    const int b  = blockIdx.y;
    const int q0 = blockIdx.x * 4;
    const int t  = threadIdx.x;

    __shared__ __align__(16) float qs[4 * D];
    __shared__ float sc[4][CAP];

    // Load 4 query rows to smem
    const float* qbase = qin + ((size_t)b * AT + q0) * D;
    for (int i = t; i < 4 * D; i += 256) qs[i] = qbase[i];
    __syncthreads();

    // Scores: one thread per (qi, k)
    {
        const int qi = t >> 6;
        const int k  = t & 63;
        const float4* sr = (const float4*)(sce + ((size_t)b * CAP + k) * D);
        const float4* qr = (const float4*)(qs + qi * D);
        float a0 = 0.f, a1 = 0.f, a2 = 0.f, a3 = 0.f;
        #pragma unroll 4
        for (int i = 0; i < D / 16; i++) {
            float4 qa = qr[4*i + 0], ca = sr[4*i + 0];
            float4 qb = qr[4*i + 1], cb = sr[4*i + 1];
            float4 qc = qr[4*i + 2], cc = sr[4*i + 2];
            float4 qd = qr[4*i + 3], cd = sr[4*i + 3];
            a0 += qa.x*ca.x + qa.y*ca.y + qa.z*ca.z + qa.w*ca.w;
            a1 += qb.x*cb.x + qb.y*cb.y + qb.z*cb.z + qb.w*cb.w;
            a2 += qc.x*cc.x + qc.y*cc.y + qc.z*cc.z + qc.w*cc.w;
            a3 += qd.x*cd.x + qd.y*cd.y + qd.z*cd.z + qd.w*cd.w;
        }
        sc[qi][k] = (a0 + a1 + a2 + a3) * rsqrtf((float)D);
    }
    __syncthreads();

    // Masked softmax per row; warps 0..3 each own one row
    {
        const int wid = t >> 5, lane = t & 31;
        if (wid < 4) {
            const int cl = clen[b];
            float v0 = (lane      < cl) ? sc[wid][lane]      : -1e9f;
            float v1 = (lane + 32 < cl) ? sc[wid][lane + 32] : -1e9f;
            float m = fmaxf(v0, v1);
            #pragma unroll
            for (int s = 16; s > 0; s >>= 1) m = fmaxf(m, __shfl_xor_sync(0xffffffff, m, s));
            float x0 = expf(v0 - m), x1 = expf(v1 - m);
            float sum = x0 + x1;
            #pragma unroll
            for (int s = 16; s > 0; s >>= 1) sum += __shfl_xor_sync(0xffffffff, sum, s);
            float inv = 1.0f / sum;
            sc[wid][lane]      = x0 * inv;
            sc[wid][lane + 32] = x1 * inv;
        }
    }
    __syncthreads();

    // Output: thread owns d = {t, t+256, t+512} for all 4 queries
    float acc[4][3] = {};
    const float* srow = sce + (size_t)b * CAP * D;
    #pragma unroll 4
    for (int k = 0; k < CAP; k++) {
        float r0 = __ldg(srow + (size_t)k * D + t);
        float r1 = __ldg(srow + (size_t)k * D + t + 256);
        float r2 = __ldg(srow + (size_t)k * D + t + 512);
        #pragma unroll
        for (int qi = 0; qi < 4; qi++) {
            float wk = sc[qi][k];
            acc[qi][0] += wk * r0;
            acc[qi][1] += wk * r1;
            acc[qi][2] += wk * r2;
        }
    }
    #pragma unroll
    for (int qi = 0; qi < 4; qi++) {
        float* orow = att + ((size_t)b * AT + q0 + qi) * D;
        orow[t]       = acc[qi][0];
        orow[t + 256] = acc[qi][1];
        orow[t + 512] = acc[qi][2];
    }
}

// ---------------------------------------------------------------------------
// Kernel 3: final variable-length scatter/select, float4 granularity
// ---------------------------------------------------------------------------
__global__ __launch_bounds__(256)
void assemble_kernel(const float* __restrict__ emb,
                     const int*   __restrict__ ids,     // [BS, SEQ]
                     const int*   __restrict__ olen,    // [BS]
                     const int*   __restrict__ tlen,    // [BS]
                     const float* __restrict__ att,     // [BS, AT, D]
                     float4*      __restrict__ out) {
    const int i = blockIdx.x * 256 + threadIdx.x;     // over BS*SEQ*(D/4)
    const int total = BS * SEQ * (D / 4);
    if (i >= total) return;
    const int d4 = i % (D / 4);
    const int bs = i / (D / 4);
    const int s  = bs & (SEQ - 1);
    const int b  = bs >> 8;

    const int rel = s - __ldg(olen + b);
    const int tl  = __ldg(tlen + b);
    const float4* src;
    if (rel >= 0 && rel < tl) {
        src = (const float4*)(att + ((size_t)b * AT + rel) * D);
    } else if (rel == tl) {
        src = (const float4*)(emb + (size_t)END_ID * D);
    } else {
        src = (const float4*)(emb + (size_t)__ldg(ids + bs) * D);
    }
    out[i] = src[d4];
}

// ---------------------------------------------------------------------------
extern "C" void kernel_launch(void* const* d_in, const int* in_sizes, int n_in,
                              void* d_out, int out_size) {
    const float* caption_out      = (const float*)d_in[0];  // [BS,CAP,VOCAB]
    const float* embed_table      = (const float*)d_in[1];  // [VOCAB,D]
    const float* inputs_embeds_at = (const float*)d_in[2];  // [BS,AT,D]
    const int*   input_ids        = (const int*)  d_in[3];  // [BS,SEQ]
    const int*   origin_len       = (const int*)  d_in[4];  // [BS]
    const int*   target_len       = (const int*)  d_in[5];  // [BS]
    const int*   caption_len      = (const int*)  d_in[6];  // [BS]
    float4* out = (float4*)d_out;

    float* sce; cudaGetSymbolAddress((void**)&sce, g_sce);
    float* att; cudaGetSymbolAddress((void**)&att, g_att);

    topk_sce_kernel<<<BS * CAP, 256>>>(caption_out, embed_table, sce);

    dim3 g2(AT / 4, BS);
    attn_kernel<<<g2, 256>>>(inputs_embeds_at, sce, caption_len, att);

    const int total = BS * SEQ * (D / 4);
    assemble_kernel<<<(total + 255) / 256, 256>>>(embed_table, input_ids,
                                                  origin_len, target_len, att, out);
}

// round 5
// speedup vs baseline: 1.2268x; 1.2268x over previous
#include <cuda_runtime.h>
#include <cuda_bf16.h>
#include <cfloat>
#include <math.h>

#define BS 16
#define CAP 64
#define VOCAB 50265
#define TOPK 5
#define SEQ 256
#define AT 32
#define D 768
#define END_ID 2
#define CAND_MAX 1024
#define ROWS_PER_BLOCK 2

// Scratch (allocation-free rule: __device__ globals)
__device__ float g_sce[BS * CAP * D];   // 3.1 MB
__device__ float g_att[BS * AT * D];    // 1.5 MB

// ---------------------------------------------------------------------------
// small branchy insert — used ONLY on tiny candidate sets (<= ~15 elements)
// ---------------------------------------------------------------------------
__device__ __forceinline__ void tk_insert(float v, int idx, float lv[5], int li[5]) {
    if (v <= lv[4]) return;
    if (v > lv[2]) {
        if (v > lv[1]) {
            if (v > lv[0]) {
                lv[4]=lv[3]; li[4]=li[3]; lv[3]=lv[2]; li[3]=li[2];
                lv[2]=lv[1]; li[2]=li[1]; lv[1]=lv[0]; li[1]=li[0];
                lv[0]=v; li[0]=idx;
            } else {
                lv[4]=lv[3]; li[4]=li[3]; lv[3]=lv[2]; li[3]=li[2];
                lv[2]=lv[1]; li[2]=li[1]; lv[1]=v; li[1]=idx;
            }
        } else {
            lv[4]=lv[3]; li[4]=li[3]; lv[3]=lv[2]; li[3]=li[2];
            lv[2]=v; li[2]=idx;
        }
    } else {
        if (v > lv[3]) {
            lv[4]=lv[3]; li[4]=li[3]; lv[3]=v; li[3]=idx;
        } else {
            lv[4]=v; li[4]=idx;
        }
    }
}

__device__ __forceinline__ float max4(float4 a) {
    return fmaxf(fmaxf(a.x, a.y), fmaxf(a.z, a.w));
}

__device__ __forceinline__ void cand4(float4 x, int idx0, float T,
                                      int* cnt, float* cval, int* cidx) {
    if (x.x >= T) { int p = atomicAdd(cnt, 1); if (p < CAND_MAX) { cval[p] = x.x; cidx[p] = idx0; } }
    if (x.y >= T) { int p = atomicAdd(cnt, 1); if (p < CAND_MAX) { cval[p] = x.y; cidx[p] = idx0 + 1; } }
    if (x.z >= T) { int p = atomicAdd(cnt, 1); if (p < CAND_MAX) { cval[p] = x.z; cidx[p] = idx0 + 2; } }
    if (x.w >= T) { int p = atomicAdd(cnt, 1); if (p < CAND_MAX) { cval[p] = x.w; cidx[p] = idx0 + 3; } }
}

// ---------------------------------------------------------------------------
// Kernel 1: two-pass threshold top-5 -> softmax -> weighted embed gather.
// grid = 512 blocks, 2 rows each (keeps L2 footprint ~103MB so pass 2 hits L2)
// ---------------------------------------------------------------------------
__global__ __launch_bounds__(256, 4)
void topk_sce_kernel(const float* __restrict__ cap_out,
                     const float* __restrict__ emb,
                     float* __restrict__ sce) {
    __shared__ float sv[256];
    __shared__ int   si[256];
    __shared__ float topv[TOPK];
    __shared__ int   topid[TOPK];
    __shared__ float wsh[TOPK];
    __shared__ int   cnt;
    __shared__ float cval[CAND_MAX];
    __shared__ int   cidx[CAND_MAX];

    const int t = threadIdx.x;

    for (int rr = 0; rr < ROWS_PER_BLOCK; rr++) {
        const int row = blockIdx.x * ROWS_PER_BLOCK + rr;
        const float* base = cap_out + (size_t)row * VOCAB;
        // VOCAB % 4 == 1  =>  (row*VOCAB) % 4 == row % 4
        const int pre  = (4 - (row & 3)) & 3;
        const int n4   = (VOCAB - pre) >> 2;
        const int done = pre + (n4 << 2);
        const float4* v4 = (const float4*)(base + pre);

        // ---------------- pass 1: branchless per-thread max, MLP=4 ----------
        float m = -FLT_MAX;
        int i = t;
        for (; i + 768 < n4; i += 1024) {
            float4 a = v4[i];
            float4 b = v4[i + 256];
            float4 c = v4[i + 512];
            float4 d = v4[i + 768];
            m = fmaxf(m, fmaxf(fmaxf(max4(a), max4(b)), fmaxf(max4(c), max4(d))));
        }
        for (; i < n4; i += 256) m = fmaxf(m, max4(v4[i]));
        if (t < pre)          m = fmaxf(m, base[t]);
        if (t < VOCAB - done) m = fmaxf(m, base[done + t]);

        // ---------------- T = 5th largest of the 256 thread maxes -----------
        // Sound: the 5 largest thread-maxes are 5 distinct elements, so the
        // true 5th-largest element of the row is >= T.
        float mv = m;
        float T = -FLT_MAX;
        for (int r = 0; r < TOPK; r++) {
            sv[t] = mv;
            __syncthreads();
            #pragma unroll
            for (int s = 128; s > 0; s >>= 1) {
                if (t < s) sv[t] = fmaxf(sv[t], sv[t + s]);
                __syncthreads();
            }
            T = sv[0];
            if (mv == T) mv = -FLT_MAX;
            __syncthreads();
        }

        if (t == 0) cnt = 0;
        __syncthreads();

        // ---------------- pass 2: collect candidates >= T (L2-hot) ----------
        i = t;
        for (; i + 768 < n4; i += 1024) {
            float4 a = v4[i];
            float4 b = v4[i + 256];
            float4 c = v4[i + 512];
            float4 d = v4[i + 768];
            int i0 = pre + (i << 2);
            if (max4(a) >= T) cand4(a, i0,        T, &cnt, cval, cidx);
            if (max4(b) >= T) cand4(b, i0 + 1024, T, &cnt, cval, cidx);
            if (max4(c) >= T) cand4(c, i0 + 2048, T, &cnt, cval, cidx);
            if (max4(d) >= T) cand4(d, i0 + 3072, T, &cnt, cval, cidx);
        }
        for (; i < n4; i += 256) {
            float4 a = v4[i];
            if (max4(a) >= T) cand4(a, pre + (i << 2), T, &cnt, cval, cidx);
        }
        if (t < pre) {
            float v = base[t];
            if (v >= T) { int p = atomicAdd(&cnt, 1); if (p < CAND_MAX) { cval[p] = v; cidx[p] = t; } }
        }
        if (t < VOCAB - done) {
            float v = base[done + t];
            if (v >= T) { int p = atomicAdd(&cnt, 1); if (p < CAND_MAX) { cval[p] = v; cidx[p] = done + t; } }
        }
        __syncthreads();

        // ---------------- exact top-5 of candidates (tiny) -------------------
        float lv[5] = {-FLT_MAX, -FLT_MAX, -FLT_MAX, -FLT_MAX, -FLT_MAX};
        int   li[5] = {0x7fffffff, 0x7fffffff, 0x7fffffff, 0x7fffffff, 0x7fffffff};
        const int C = (cnt < CAND_MAX) ? cnt : CAND_MAX;
        for (int j = t; j < C; j += 256) tk_insert(cval[j], cidx[j], lv, li);

        int ptr = 0;
        for (int r = 0; r < TOPK; r++) {
            sv[t] = (ptr < 5) ? lv[ptr] : -FLT_MAX;
            si[t] = (ptr < 5) ? li[ptr] : 0x7fffffff;
            __syncthreads();
            #pragma unroll
            for (int s = 128; s > 0; s >>= 1) {
                if (t < s) {
                    float ov = sv[t + s]; int oi = si[t + s];
                    if (ov > sv[t] || (ov == sv[t] && oi < si[t])) { sv[t] = ov; si[t] = oi; }
                }
                __syncthreads();
            }
            if (t == 0) { topv[r] = sv[0]; topid[r] = si[0]; }
            int win = si[0];
            if (ptr < 5 && li[ptr] == win) ptr++;
            __syncthreads();
        }

        // ---------------- softmax over 5 -------------------------------------
        if (t == 0) {
            float mm = topv[0];
            float e0 = expf(topv[0] - mm), e1 = expf(topv[1] - mm), e2 = expf(topv[2] - mm);
            float e3 = expf(topv[3] - mm), e4 = expf(topv[4] - mm);
            float inv = 1.0f / (e0 + e1 + e2 + e3 + e4);
            wsh[0]=e0*inv; wsh[1]=e1*inv; wsh[2]=e2*inv; wsh[3]=e3*inv; wsh[4]=e4*inv;
        }
        __syncthreads();

        // ---------------- weighted embed gather ------------------------------
        const float* e0 = emb + (size_t)topid[0] * D;
        const float* e1 = emb + (size_t)topid[1] * D;
        const float* e2 = emb + (size_t)topid[2] * D;
        const float* e3 = emb + (size_t)topid[3] * D;
        const float* e4 = emb + (size_t)topid[4] * D;
        float w0 = wsh[0], w1 = wsh[1], w2 = wsh[2], w3 = wsh[3], w4 = wsh[4];
        float* srow = sce + (size_t)row * D;
        #pragma unroll
        for (int d = t; d < D; d += 256) {
            srow[d] = w0*__ldg(e0+d) + w1*__ldg(e1+d) + w2*__ldg(e2+d)
                    + w3*__ldg(e3+d) + w4*__ldg(e4+d);
        }
        __syncthreads();   // protect shared reuse across rows
    }
}

// ---------------------------------------------------------------------------
// Kernel 2: attention  (block = (qtile of 4, b)), 256 threads, coalesced
// ---------------------------------------------------------------------------
__global__ __launch_bounds__(256, 4)
void attn_kernel(const float* __restrict__ qin,     // [BS, AT, D]
                 const float* __restrict__ sce,     // [BS, CAP, D]
                 const int*   __restrict__ clen,    // [BS]
                 float*       __restrict__ att) {   // [BS, AT, D]
    const int b  = blockIdx.y;
    const int q0 = blockIdx.x * 4;
    const int t  = threadIdx.x;
    const int wid = t >> 5, lane = t & 31;

    __shared__ __align__(16) float qs[4 * D];
    __shared__ float sc[4][CAP];

    // Load 4 query rows to smem (coalesced)
    const float* qbase = qin + ((size_t)b * AT + q0) * D;
    for (int i = t; i < 4 * D; i += 256) qs[i] = qbase[i];
    __syncthreads();

    // Scores: warp w handles keys k = w*8 .. w*8+7; lanes stride D (coalesced)
    {
        const float4* qs4 = (const float4*)qs;
        #pragma unroll
        for (int kk = 0; kk < 8; kk++) {
            const int k = wid * 8 + kk;
            const float4* kr = (const float4*)(sce + ((size_t)b * CAP + k) * D);
            float acc0 = 0.f, acc1 = 0.f, acc2 = 0.f, acc3 = 0.f;
            #pragma unroll
            for (int j = 0; j < D / 128; j++) {           // 6 iters, lane-strided
                float4 kv = kr[lane + 32 * j];
                float4 q0v = qs4[0 * (D/4) + lane + 32 * j];
                float4 q1v = qs4[1 * (D/4) + lane + 32 * j];
                float4 q2v = qs4[2 * (D/4) + lane + 32 * j];
                float4 q3v = qs4[3 * (D/4) + lane + 32 * j];
                acc0 += kv.x*q0v.x + kv.y*q0v.y + kv.z*q0v.z + kv.w*q0v.w;
                acc1 += kv.x*q1v.x + kv.y*q1v.y + kv.z*q1v.z + kv.w*q1v.w;
                acc2 += kv.x*q2v.x + kv.y*q2v.y + kv.z*q2v.z + kv.w*q2v.w;
                acc3 += kv.x*q3v.x + kv.y*q3v.y + kv.z*q3v.z + kv.w*q3v.w;
            }
            #pragma unroll
            for (int s = 16; s > 0; s >>= 1) {
                acc0 += __shfl_xor_sync(0xffffffffu, acc0, s);
                acc1 += __shfl_xor_sync(0xffffffffu, acc1, s);
                acc2 += __shfl_xor_sync(0xffffffffu, acc2, s);
                acc3 += __shfl_xor_sync(0xffffffffu, acc3, s);
            }
            if (lane == 0) {
                const float scale = rsqrtf((float)D);
                sc[0][k] = acc0 * scale;
                sc[1][k] = acc1 * scale;
                sc[2][k] = acc2 * scale;
                sc[3][k] = acc3 * scale;
            }
        }
    }
    __syncthreads();

    // Masked softmax per query row; warps 0..3 each own one row
    if (wid < 4) {
        const int cl = clen[b];
        float v0 = (lane      < cl) ? sc[wid][lane]      : -1e9f;
        float v1 = (lane + 32 < cl) ? sc[wid][lane + 32] : -1e9f;
        float m = fmaxf(v0, v1);
        #pragma unroll
        for (int s = 16; s > 0; s >>= 1) m = fmaxf(m, __shfl_xor_sync(0xffffffffu, m, s));
        float x0 = expf(v0 - m), x1 = expf(v1 - m);
        float sum = x0 + x1;
        #pragma unroll
        for (int s = 16; s > 0; s >>= 1) sum += __shfl_xor_sync(0xffffffffu, sum, s);
        float inv = 1.0f / sum;
        sc[wid][lane]      = x0 * inv;
        sc[wid][lane + 32] = x1 * inv;
    }
    __syncthreads();

    // Output: thread owns d = {t, t+256, t+512} for all 4 queries (coalesced)
    float acc[4][3] = {};
    const float* srow = sce + (size_t)b * CAP * D;
    #pragma unroll 4
    for (int k = 0; k < CAP; k++) {
        float r0 = __ldg(srow + (size_t)k * D + t);
        float r1 = __ldg(srow + (size_t)k * D + t + 256);
        float r2 = __ldg(srow + (size_t)k * D + t + 512);
        #pragma unroll
        for (int qi = 0; qi < 4; qi++) {
            float wk = sc[qi][k];
            acc[qi][0] += wk * r0;
            acc[qi][1] += wk * r1;
            acc[qi][2] += wk * r2;
        }
    }
    #pragma unroll
    for (int qi = 0; qi < 4; qi++) {
        float* orow = att + ((size_t)b * AT + q0 + qi) * D;
        orow[t]       = acc[qi][0];
        orow[t + 256] = acc[qi][1];
        orow[t + 512] = acc[qi][2];
    }
}

// ---------------------------------------------------------------------------
// Kernel 3: final variable-length scatter/select, float4 granularity
// ---------------------------------------------------------------------------
__global__ __launch_bounds__(256)
void assemble_kernel(const float* __restrict__ emb,
                     const int*   __restrict__ ids,     // [BS, SEQ]
                     const int*   __restrict__ olen,    // [BS]
                     const int*   __restrict__ tlen,    // [BS]
                     const float* __restrict__ att,     // [BS, AT, D]
                     float4*      __restrict__ out) {
    const int i = blockIdx.x * 256 + threadIdx.x;     // over BS*SEQ*(D/4)
    const int total = BS * SEQ * (D / 4);
    if (i >= total) return;
    const int d4 = i % (D / 4);
    const int bs = i / (D / 4);
    const int s  = bs & (SEQ - 1);
    const int b  = bs >> 8;

    const int rel = s - __ldg(olen + b);
    const int tl  = __ldg(tlen + b);
    const float4* src;
    if (rel >= 0 && rel < tl) {
        src = (const float4*)(att + ((size_t)b * AT + rel) * D);
    } else if (rel == tl) {
        src = (const float4*)(emb + (size_t)END_ID * D);
    } else {
        src = (const float4*)(emb + (size_t)__ldg(ids + bs) * D);
    }
    out[i] = src[d4];
}

// ---------------------------------------------------------------------------
extern "C" void kernel_launch(void* const* d_in, const int* in_sizes, int n_in,
                              void* d_out, int out_size) {
    const float* caption_out      = (const float*)d_in[0];  // [BS,CAP,VOCAB]
    const float* embed_table      = (const float*)d_in[1];  // [VOCAB,D]
    const float* inputs_embeds_at = (const float*)d_in[2];  // [BS,AT,D]
    const int*   input_ids        = (const int*)  d_in[3];  // [BS,SEQ]
    const int*   origin_len       = (const int*)  d_in[4];  // [BS]
    const int*   target_len       = (const int*)  d_in[5];  // [BS]
    const int*   caption_len      = (const int*)  d_in[6];  // [BS]
    float4* out = (float4*)d_out;

    float* sce; cudaGetSymbolAddress((void**)&sce, g_sce);
    float* att; cudaGetSymbolAddress((void**)&att, g_att);

    topk_sce_kernel<<<(BS * CAP) / ROWS_PER_BLOCK, 256>>>(caption_out, embed_table, sce);

    dim3 g2(AT / 4, BS);
    attn_kernel<<<g2, 256>>>(inputs_embeds_at, sce, caption_len, att);

    const int total = BS * SEQ * (D / 4);
    assemble_kernel<<<(total + 255) / 256, 256>>>(embed_table, input_ids,
                                                  origin_len, target_len, att, out);
}

// round 9
// speedup vs baseline: 1.3197x; 1.0757x over previous
#include <cuda_runtime.h>
#include <cuda_bf16.h>
#include <cfloat>
#include <math.h>

#define BS 16
#define CAP 64
#define VOCAB 50265
#define TOPK 5
#define SEQ 256
#define AT 32
#define D 768
#define END_ID 2
#define CAND_MAX 512

// max float4s per half-row: n4<=12566 -> ceil/2 = 6283
#define HALF_F4_MAX 6283
#define SMEM_DYN (HALF_F4_MAX * 16)

// Scratch (allocation-free rule: __device__ globals)
__device__ float g_sce[BS * CAP * D];          // 3.1 MB
__device__ float g_att[BS * AT * D];           // 1.5 MB
__device__ float g_topv[BS * CAP * 2 * TOPK];  // per-half top-5 values
__device__ int   g_topi[BS * CAP * 2 * TOPK];  // per-half top-5 indices

// ---------------------------------------------------------------------------
__device__ __forceinline__ float max4(float4 a) {
    return fmaxf(fmaxf(a.x, a.y), fmaxf(a.z, a.w));
}

// small branchy insert — used ONLY on tiny candidate sets
__device__ __forceinline__ void tk_insert(float v, int idx, float lv[5], int li[5]) {
    if (v <= lv[4]) return;
    if (v > lv[2]) {
        if (v > lv[1]) {
            if (v > lv[0]) {
                lv[4]=lv[3]; li[4]=li[3]; lv[3]=lv[2]; li[3]=li[2];
                lv[2]=lv[1]; li[2]=li[1]; lv[1]=lv[0]; li[1]=li[0];
                lv[0]=v; li[0]=idx;
            } else {
                lv[4]=lv[3]; li[4]=li[3]; lv[3]=lv[2]; li[3]=li[2];
                lv[2]=lv[1]; li[2]=li[1]; lv[1]=v; li[1]=idx;
            }
        } else {
            lv[4]=lv[3]; li[4]=li[3]; lv[3]=lv[2]; li[3]=li[2];
            lv[2]=v; li[2]=idx;
        }
    } else {
        if (v > lv[3]) {
            lv[4]=lv[3]; li[4]=li[3]; lv[3]=v; li[3]=idx;
        } else {
            lv[4]=v; li[4]=idx;
        }
    }
}

__device__ __forceinline__ void cand4(float4 x, int idx0, float T,
                                      int* cnt, float* cval, int* cidx) {
    if (x.x >= T) { int p = atomicAdd(cnt, 1); if (p < CAND_MAX) { cval[p] = x.x; cidx[p] = idx0; } }
    if (x.y >= T) { int p = atomicAdd(cnt, 1); if (p < CAND_MAX) { cval[p] = x.y; cidx[p] = idx0 + 1; } }
    if (x.z >= T) { int p = atomicAdd(cnt, 1); if (p < CAND_MAX) { cval[p] = x.z; cidx[p] = idx0 + 2; } }
    if (x.w >= T) { int p = atomicAdd(cnt, 1); if (p < CAND_MAX) { cval[p] = x.w; cidx[p] = idx0 + 3; } }
}

#define CP_ASYNC_CG(dst_u32, src_ptr) \
    asm volatile("cp.async.cg.shared.global [%0], [%1], 16;" \
                 :: "r"(dst_u32), "l"(src_ptr) : "memory")
#define CP_COMMIT() asm volatile("cp.async.commit_group;" ::: "memory")

// ---------------------------------------------------------------------------
// Stage 1: per-half-row exact top-5 via SMEM staging (single DRAM read)
// grid = BS*CAP*2, block = 256, dynamic smem = SMEM_DYN (2 CTAs/SM)
// ---------------------------------------------------------------------------
__global__ __launch_bounds__(256, 2)
void topk_half_kernel(const float* __restrict__ cap_out,
                      float* __restrict__ outv,
                      int*   __restrict__ outi) {
    extern __shared__ __align__(16) float4 buf[];
    __shared__ float warpT[8];
    __shared__ float Tsh;
    __shared__ int   cnt;
    __shared__ float cval[CAND_MAX];
    __shared__ int   cidx[CAND_MAX];

    const int t    = threadIdx.x;
    const int lane = t & 31, wid = t >> 5;
    const int cta  = blockIdx.x;
    const int row  = cta >> 1;
    const int half = cta & 1;

    const float* base = cap_out + (size_t)row * VOCAB;
    const int pre  = (4 - (row & 3)) & 3;          // VOCAB%4==1 -> base misalign = row%4
    const int n4   = (VOCAB - pre) >> 2;
    const int h4   = n4 >> 1;
    const int f0   = half ? h4 : 0;
    const int nf   = (half ? n4 : h4) - f0;        // <= 6283
    const int done = pre + (n4 << 2);
    const int ntail = VOCAB - done;                // 0..3
    const float4* src = (const float4*)(base + pre) + f0;

    // ---- issue all cp.async copies: 5 groups of 5 strided slots/thread -----
    unsigned saddr = (unsigned)__cvta_generic_to_shared(buf);
    #pragma unroll
    for (int b = 0; b < 5; b++) {
        #pragma unroll
        for (int u = 0; u < 5; u++) {
            int j = t + 256 * (b * 5 + u);
            if (j < nf) CP_ASYNC_CG(saddr + j * 16, src + j);
        }
        CP_COMMIT();
    }

    // boundary scalars (half0: pre, half1: tail) while copies fly
    float m = -FLT_MAX;
    if (half == 0) { if (t < pre)   m = fmaxf(m, base[t]); }
    else           { if (t < ntail) m = fmaxf(m, base[done + t]); }

    // ---- pass 1: per-thread max from own smem slots, batch-pipelined -------
    #pragma unroll
    for (int b = 0; b < 5; b++) {
        if      (b == 0) asm volatile("cp.async.wait_group 4;" ::: "memory");
        else if (b == 1) asm volatile("cp.async.wait_group 3;" ::: "memory");
        else if (b == 2) asm volatile("cp.async.wait_group 2;" ::: "memory");
        else if (b == 3) asm volatile("cp.async.wait_group 1;" ::: "memory");
        else             asm volatile("cp.async.wait_group 0;" ::: "memory");
        #pragma unroll
        for (int u = 0; u < 5; u++) {
            int j = t + 256 * (b * 5 + u);
            if (j < nf) m = fmaxf(m, max4(buf[j]));
        }
    }

    // ---- threshold: T = max over warps of (5th distinct largest thread-max)
    // Sound: the warp attaining the max exhibits 5 distinct elements >= T,
    // so the half's true 5th-largest element >= T.
    {
        float mv = m, Tw = -FLT_MAX;
        #pragma unroll
        for (int r = 0; r < TOPK; r++) {
            float bv = mv;
            #pragma unroll
            for (int s = 16; s > 0; s >>= 1)
                bv = fmaxf(bv, __shfl_xor_sync(0xffffffffu, bv, s));
            Tw = bv;
            if (mv == bv) mv = -FLT_MAX;
        }
        if (lane == 0) warpT[wid] = Tw;
    }
    if (t == 0) cnt = 0;
    __syncthreads();
    {
        float T = warpT[0];
        #pragma unroll
        for (int w = 1; w < 8; w++) T = fmaxf(T, warpT[w]);
        if (t == 0) Tsh = T;
    }
    __syncthreads();
    const float T = Tsh;

    // ---- pass 2: rescan own smem slots, collect candidates >= T ------------
    #pragma unroll
    for (int b = 0; b < 25; b++) {
        int j = t + 256 * b;
        if (j < nf) {
            float4 a = buf[j];
            if (max4(a) >= T) cand4(a, pre + 4 * (f0 + j), T, &cnt, cval, cidx);
        }
    }
    if (half == 0) {
        if (t < pre) {
            float v = base[t];
            if (v >= T) { int p = atomicAdd(&cnt, 1); if (p < CAND_MAX) { cval[p] = v; cidx[p] = t; } }
        }
    } else {
        if (t < ntail) {
            float v = base[done + t];
            if (v >= T) { int p = atomicAdd(&cnt, 1); if (p < CAND_MAX) { cval[p] = v; cidx[p] = done + t; } }
        }
    }
    __syncthreads();

    // ---- exact top-5 of candidates: warp 0 only ----------------------------
    if (wid == 0) {
        const int C = (cnt < CAND_MAX) ? cnt : CAND_MAX;
        float lv[5] = {-FLT_MAX, -FLT_MAX, -FLT_MAX, -FLT_MAX, -FLT_MAX};
        int   li[5] = {0x7fffffff, 0x7fffffff, 0x7fffffff, 0x7fffffff, 0x7fffffff};
        for (int j = lane; j < C; j += 32) tk_insert(cval[j], cidx[j], lv, li);

        int ptr = 0;
        #pragma unroll
        for (int r = 0; r < TOPK; r++) {
            float bv = (ptr < 5) ? lv[ptr] : -FLT_MAX;
            int   bi = (ptr < 5) ? li[ptr] : 0x7fffffff;
            #pragma unroll
            for (int s = 16; s > 0; s >>= 1) {
                float ov = __shfl_xor_sync(0xffffffffu, bv, s);
                int   oi = __shfl_xor_sync(0xffffffffu, bi, s);
                if (ov > bv || (ov == bv && oi < bi)) { bv = ov; bi = oi; }
            }
            if (ptr < 5 && li[ptr] == bi && lv[ptr] == bv) ptr++;
            if (lane == 0) {
                outv[cta * TOPK + r] = bv;
                outi[cta * TOPK + r] = bi;
            }
        }
    }
}

// ---------------------------------------------------------------------------
// Stage 2: merge halves -> softmax-of-5 -> weighted embed gather
// grid = BS*CAP, block = 256
// ---------------------------------------------------------------------------
__global__ __launch_bounds__(256)
void merge_sce_kernel(const float* __restrict__ inv,
                      const int*   __restrict__ ini,
                      const float* __restrict__ emb,
                      float* __restrict__ sce) {
    const int row = blockIdx.x;
    const int t   = threadIdx.x;
    __shared__ float wsh[TOPK];
    __shared__ int   ids[TOPK];

    if (t == 0) {
        float lv[5] = {-FLT_MAX, -FLT_MAX, -FLT_MAX, -FLT_MAX, -FLT_MAX};
        int   li[5] = {0x7fffffff, 0x7fffffff, 0x7fffffff, 0x7fffffff, 0x7fffffff};
        #pragma unroll
        for (int h = 0; h < 2; h++)
            #pragma unroll
            for (int r = 0; r < TOPK; r++) {
                int s = (row * 2 + h) * TOPK + r;
                tk_insert(inv[s], ini[s], lv, li);
            }
        float mm = lv[0];
        float e0 = expf(lv[0] - mm), e1 = expf(lv[1] - mm), e2 = expf(lv[2] - mm);
        float e3 = expf(lv[3] - mm), e4 = expf(lv[4] - mm);
        float inv5 = 1.0f / (e0 + e1 + e2 + e3 + e4);
        wsh[0]=e0*inv5; wsh[1]=e1*inv5; wsh[2]=e2*inv5; wsh[3]=e3*inv5; wsh[4]=e4*inv5;
        ids[0]=li[0]; ids[1]=li[1]; ids[2]=li[2]; ids[3]=li[3]; ids[4]=li[4];
    }
    __syncthreads();

    const float* e0 = emb + (size_t)ids[0] * D;
    const float* e1 = emb + (size_t)ids[1] * D;
    const float* e2 = emb + (size_t)ids[2] * D;
    const float* e3 = emb + (size_t)ids[3] * D;
    const float* e4 = emb + (size_t)ids[4] * D;
    float w0 = wsh[0], w1 = wsh[1], w2 = wsh[2], w3 = wsh[3], w4 = wsh[4];
    float* srow = sce + (size_t)row * D;
    #pragma unroll
    for (int d = t; d < D; d += 256) {
        srow[d] = w0*__ldg(e0+d) + w1*__ldg(e1+d) + w2*__ldg(e2+d)
                + w3*__ldg(e3+d) + w4*__ldg(e4+d);
    }
}

// ---------------------------------------------------------------------------
// Kernel 2: attention  (block = (qtile of 4, b)), 256 threads, coalesced
// ---------------------------------------------------------------------------
__global__ __launch_bounds__(256, 4)
void attn_kernel(const float* __restrict__ qin,     // [BS, AT, D]
                 const float* __restrict__ sce,     // [BS, CAP, D]
                 const int*   __restrict__ clen,    // [BS]
                 float*       __restrict__ att) {   // [BS, AT, D]
    const int b  = blockIdx.y;
    const int q0 = blockIdx.x * 4;
    const int t  = threadIdx.x;
    const int wid = t >> 5, lane = t & 31;

    __shared__ __align__(16) float qs[4 * D];
    __shared__ float sc[4][CAP];

    const float* qbase = qin + ((size_t)b * AT + q0) * D;
    for (int i = t; i < 4 * D; i += 256) qs[i] = qbase[i];
    __syncthreads();

    {
        const float4* qs4 = (const float4*)qs;
        #pragma unroll
        for (int kk = 0; kk < 8; kk++) {
            const int k = wid * 8 + kk;
            const float4* kr = (const float4*)(sce + ((size_t)b * CAP + k) * D);
            float acc0 = 0.f, acc1 = 0.f, acc2 = 0.f, acc3 = 0.f;
            #pragma unroll
            for (int j = 0; j < D / 128; j++) {
                float4 kv = kr[lane + 32 * j];
                float4 q0v = qs4[0 * (D/4) + lane + 32 * j];
                float4 q1v = qs4[1 * (D/4) + lane + 32 * j];
                float4 q2v = qs4[2 * (D/4) + lane + 32 * j];
                float4 q3v = qs4[3 * (D/4) + lane + 32 * j];
                acc0 += kv.x*q0v.x + kv.y*q0v.y + kv.z*q0v.z + kv.w*q0v.w;
                acc1 += kv.x*q1v.x + kv.y*q1v.y + kv.z*q1v.z + kv.w*q1v.w;
                acc2 += kv.x*q2v.x + kv.y*q2v.y + kv.z*q2v.z + kv.w*q2v.w;
                acc3 += kv.x*q3v.x + kv.y*q3v.y + kv.z*q3v.z + kv.w*q3v.w;
            }
            #pragma unroll
            for (int s = 16; s > 0; s >>= 1) {
                acc0 += __shfl_xor_sync(0xffffffffu, acc0, s);
                acc1 += __shfl_xor_sync(0xffffffffu, acc1, s);
                acc2 += __shfl_xor_sync(0xffffffffu, acc2, s);
                acc3 += __shfl_xor_sync(0xffffffffu, acc3, s);
            }
            if (lane == 0) {
                const float scale = rsqrtf((float)D);
                sc[0][k] = acc0 * scale;
                sc[1][k] = acc1 * scale;
                sc[2][k] = acc2 * scale;
                sc[3][k] = acc3 * scale;
            }
        }
    }
    __syncthreads();

    if (wid < 4) {
        const int cl = clen[b];
        float v0 = (lane      < cl) ? sc[wid][lane]      : -1e9f;
        float v1 = (lane + 32 < cl) ? sc[wid][lane + 32] : -1e9f;
        float m = fmaxf(v0, v1);
        #pragma unroll
        for (int s = 16; s > 0; s >>= 1) m = fmaxf(m, __shfl_xor_sync(0xffffffffu, m, s));
        float x0 = expf(v0 - m), x1 = expf(v1 - m);
        float sum = x0 + x1;
        #pragma unroll
        for (int s = 16; s > 0; s >>= 1) sum += __shfl_xor_sync(0xffffffffu, sum, s);
        float inv = 1.0f / sum;
        sc[wid][lane]      = x0 * inv;
        sc[wid][lane + 32] = x1 * inv;
    }
    __syncthreads();

    float acc[4][3] = {};
    const float* srow = sce + (size_t)b * CAP * D;
    #pragma unroll 4
    for (int k = 0; k < CAP; k++) {
        float r0 = __ldg(srow + (size_t)k * D + t);
        float r1 = __ldg(srow + (size_t)k * D + t + 256);
        float r2 = __ldg(srow + (size_t)k * D + t + 512);
        #pragma unroll
        for (int qi = 0; qi < 4; qi++) {
            float wk = sc[qi][k];
            acc[qi][0] += wk * r0;
            acc[qi][1] += wk * r1;
            acc[qi][2] += wk * r2;
        }
    }
    #pragma unroll
    for (int qi = 0; qi < 4; qi++) {
        float* orow = att + ((size_t)b * AT + q0 + qi) * D;
        orow[t]       = acc[qi][0];
        orow[t + 256] = acc[qi][1];
        orow[t + 512] = acc[qi][2];
    }
}

// ---------------------------------------------------------------------------
// Kernel 3: final variable-length scatter/select, float4 granularity
// ---------------------------------------------------------------------------
__global__ __launch_bounds__(256)
void assemble_kernel(const float* __restrict__ emb,
                     const int*   __restrict__ ids,     // [BS, SEQ]
                     const int*   __restrict__ olen,    // [BS]
                     const int*   __restrict__ tlen,    // [BS]
                     const float* __restrict__ att,     // [BS, AT, D]
                     float4*      __restrict__ out) {
    const int i = blockIdx.x * 256 + threadIdx.x;     // over BS*SEQ*(D/4)
    const int total = BS * SEQ * (D / 4);
    if (i >= total) return;
    const int d4 = i % (D / 4);
    const int bs = i / (D / 4);
    const int s  = bs & (SEQ - 1);
    const int b  = bs >> 8;

    const int rel = s - __ldg(olen + b);
    const int tl  = __ldg(tlen + b);
    const float4* src;
    if (rel >= 0 && rel < tl) {
        src = (const float4*)(att + ((size_t)b * AT + rel) * D);
    } else if (rel == tl) {
        src = (const float4*)(emb + (size_t)END_ID * D);
    } else {
        src = (const float4*)(emb + (size_t)__ldg(ids + bs) * D);
    }
    out[i] = src[d4];
}

// ---------------------------------------------------------------------------
extern "C" void kernel_launch(void* const* d_in, const int* in_sizes, int n_in,
                              void* d_out, int out_size) {
    const float* caption_out      = (const float*)d_in[0];  // [BS,CAP,VOCAB]
    const float* embed_table      = (const float*)d_in[1];  // [VOCAB,D]
    const float* inputs_embeds_at = (const float*)d_in[2];  // [BS,AT,D]
    const int*   input_ids        = (const int*)  d_in[3];  // [BS,SEQ]
    const int*   origin_len       = (const int*)  d_in[4];  // [BS]
    const int*   target_len       = (const int*)  d_in[5];  // [BS]
    const int*   caption_len      = (const int*)  d_in[6];  // [BS]
    float4* out = (float4*)d_out;

    float* sce;  cudaGetSymbolAddress((void**)&sce,  g_sce);
    float* att;  cudaGetSymbolAddress((void**)&att,  g_att);
    float* topv; cudaGetSymbolAddress((void**)&topv, g_topv);
    int*   topi; cudaGetSymbolAddress((void**)&topi, g_topi);

    static bool attr_set = false;
    if (!attr_set) {
        cudaFuncSetAttribute(topk_half_kernel,
                             cudaFuncAttributeMaxDynamicSharedMemorySize, SMEM_DYN);
        attr_set = true;
    }

    topk_half_kernel<<<BS * CAP * 2, 256, SMEM_DYN>>>(caption_out, topv, topi);

    merge_sce_kernel<<<BS * CAP, 256>>>(topv, topi, embed_table, sce);

    dim3 g2(AT / 4, BS);
    attn_kernel<<<g2, 256>>>(inputs_embeds_at, sce, caption_len, att);

    const int total = BS * SEQ * (D / 4);
    assemble_kernel<<<(total + 255) / 256, 256>>>(embed_table, input_ids,
                                                  origin_len, target_len, att, out);
}

// round 11
// speedup vs baseline: 1.7039x; 1.2911x over previous
#include <cuda_runtime.h>
#include <cuda_bf16.h>
#include <cfloat>
#include <math.h>

#define BS 16
#define CAP 64
#define VOCAB 50265
#define TOPK 5
#define SEQ 256
#define AT 32
#define D 768
#define END_ID 2
#define CAND_MAX 1024

// Scratch (allocation-free rule: __device__ globals)
__device__ float g_sce[BS * CAP * D];   // 3.1 MB
__device__ float g_att[BS * AT * D];    // 1.5 MB

// ---------------------------------------------------------------------------
__device__ __forceinline__ float max4(float4 a) {
    return fmaxf(fmaxf(a.x, a.y), fmaxf(a.z, a.w));
}

// small branchy insert — used ONLY on tiny candidate sets
__device__ __forceinline__ void tk_insert(float v, int idx, float lv[5], int li[5]) {
    if (v <= lv[4]) return;
    if (v > lv[2]) {
        if (v > lv[1]) {
            if (v > lv[0]) {
                lv[4]=lv[3]; li[4]=li[3]; lv[3]=lv[2]; li[3]=li[2];
                lv[2]=lv[1]; li[2]=li[1]; lv[1]=lv[0]; li[1]=li[0];
                lv[0]=v; li[0]=idx;
            } else {
                lv[4]=lv[3]; li[4]=li[3]; lv[3]=lv[2]; li[3]=li[2];
                lv[2]=lv[1]; li[2]=li[1]; lv[1]=v; li[1]=idx;
            }
        } else {
            lv[4]=lv[3]; li[4]=li[3]; lv[3]=lv[2]; li[3]=li[2];
            lv[2]=v; li[2]=idx;
        }
    } else {
        if (v > lv[3]) {
            lv[4]=lv[3]; li[4]=li[3]; lv[3]=v; li[3]=idx;
        } else {
            lv[4]=v; li[4]=idx;
        }
    }
}

__device__ __forceinline__ void cand4(float4 x, int idx0, float T,
                                      int* cnt, float* cval, int* cidx) {
    if (x.x >= T) { int p = atomicAdd(cnt, 1); if (p < CAND_MAX) { cval[p] = x.x; cidx[p] = idx0; } }
    if (x.y >= T) { int p = atomicAdd(cnt, 1); if (p < CAND_MAX) { cval[p] = x.y; cidx[p] = idx0 + 1; } }
    if (x.z >= T) { int p = atomicAdd(cnt, 1); if (p < CAND_MAX) { cval[p] = x.z; cidx[p] = idx0 + 2; } }
    if (x.w >= T) { int p = atomicAdd(cnt, 1); if (p < CAND_MAX) { cval[p] = x.w; cidx[p] = idx0 + 3; } }
}

// ---------------------------------------------------------------------------
// Stage 1: one-pass threshold top-5 -> softmax -> weighted embed gather.
// grid = BS*CAP (row per CTA), 256 threads.
// Warm-up on first 2048 elements gives a sound threshold T (<= true 5th),
// then a single streaming pass collects ~123 expected candidates.
// ---------------------------------------------------------------------------
__global__ __launch_bounds__(256, 4)
void topk_sce_kernel(const float* __restrict__ cap_out,
                     const float* __restrict__ emb,
                     float* __restrict__ sce) {
    __shared__ float warm[8 * TOPK];
    __shared__ float Tsh;
    __shared__ int   cnt;
    __shared__ float cval[CAND_MAX];
    __shared__ int   cidx[CAND_MAX];
    __shared__ float wsh[TOPK];
    __shared__ int   ids[TOPK];

    const int t    = threadIdx.x;
    const int lane = t & 31, wid = t >> 5;
    const int row  = blockIdx.x;

    const float* base = cap_out + (size_t)row * VOCAB;
    const int pre   = (4 - (row & 3)) & 3;         // VOCAB%4==1 -> misalign = row%4
    const int n4    = (VOCAB - pre) >> 2;
    const int done  = pre + (n4 << 2);
    const int ntail = VOCAB - done;                // 0..3
    const float4* v4 = (const float4*)(base + pre);

    // ---- warm-up: 2 f4 per thread (first 2048 elements), kept in registers
    float4 w0 = v4[t];
    float4 w1 = v4[t + 256];
    float m = fmaxf(max4(w0), max4(w1));

    // ---- per-warp top-5 of thread maxes (shuffles only) --------------------
    {
        float mv = m;
        #pragma unroll
        for (int r = 0; r < TOPK; r++) {
            float bv = mv; int bl = lane;
            #pragma unroll
            for (int s = 16; s > 0; s >>= 1) {
                float ov = __shfl_xor_sync(0xffffffffu, bv, s);
                int   ol = __shfl_xor_sync(0xffffffffu, bl, s);
                if (ov > bv || (ov == bv && ol < bl)) { bv = ov; bl = ol; }
            }
            if (lane == 0) warm[wid * TOPK + r] = bv;
            if (lane == bl) mv = -FLT_MAX;
        }
    }
    if (t == 0) cnt = 0;
    __syncthreads();

    // ---- warp 0: T = 5th largest of the 40 per-warp winners ----------------
    // Sound: the 5 largest thread-maxes are 5 distinct elements of the sample,
    // so sample-5th >= T, and row-5th >= sample-5th >= T.
    if (wid == 0) {
        float lv[5] = {-FLT_MAX, -FLT_MAX, -FLT_MAX, -FLT_MAX, -FLT_MAX};
        int   li[5] = {0x7fffffff, 0x7fffffff, 0x7fffffff, 0x7fffffff, 0x7fffffff};
        for (int j = lane; j < 8 * TOPK; j += 32) tk_insert(warm[j], j, lv, li);
        int ptr = 0;
        float last = -FLT_MAX;
        #pragma unroll
        for (int r = 0; r < TOPK; r++) {
            float bv = (ptr < 5) ? lv[ptr] : -FLT_MAX;
            int   bi = (ptr < 5) ? li[ptr] : 0x7fffffff;
            #pragma unroll
            for (int s = 16; s > 0; s >>= 1) {
                float ov = __shfl_xor_sync(0xffffffffu, bv, s);
                int   oi = __shfl_xor_sync(0xffffffffu, bi, s);
                if (ov > bv || (ov == bv && oi < bi)) { bv = ov; bi = oi; }
            }
            if (ptr < 5 && li[ptr] == bi && lv[ptr] == bv) ptr++;
            last = bv;
        }
        if (lane == 0) Tsh = last;
    }
    __syncthreads();
    const float T = Tsh;

    // ---- single streaming pass: collect candidates >= T --------------------
    if (max4(w0) >= T) cand4(w0, pre + 4 * t,         T, &cnt, cval, cidx);
    if (max4(w1) >= T) cand4(w1, pre + 4 * (t + 256), T, &cnt, cval, cidx);

    int j = 512 + t;
    for (; j + 768 < n4; j += 1024) {
        float4 a = __ldcs(v4 + j);
        float4 b = __ldcs(v4 + j + 256);
        float4 c = __ldcs(v4 + j + 512);
        float4 d = __ldcs(v4 + j + 768);
        if (max4(a) >= T) cand4(a, pre + 4 * j,         T, &cnt, cval, cidx);
        if (max4(b) >= T) cand4(b, pre + 4 * (j + 256), T, &cnt, cval, cidx);
        if (max4(c) >= T) cand4(c, pre + 4 * (j + 512), T, &cnt, cval, cidx);
        if (max4(d) >= T) cand4(d, pre + 4 * (j + 768), T, &cnt, cval, cidx);
    }
    for (; j < n4; j += 256) {
        float4 a = __ldcs(v4 + j);
        if (max4(a) >= T) cand4(a, pre + 4 * j, T, &cnt, cval, cidx);
    }
    if (t < pre) {
        float v = base[t];
        if (v >= T) { int p = atomicAdd(&cnt, 1); if (p < CAND_MAX) { cval[p] = v; cidx[p] = t; } }
    }
    if (t < ntail) {
        float v = base[done + t];
        if (v >= T) { int p = atomicAdd(&cnt, 1); if (p < CAND_MAX) { cval[p] = v; cidx[p] = done + t; } }
    }
    __syncthreads();

    // ---- exact top-5 of candidates + softmax (warp 0) ----------------------
    if (wid == 0) {
        const int C = (cnt < CAND_MAX) ? cnt : CAND_MAX;
        float lv[5] = {-FLT_MAX, -FLT_MAX, -FLT_MAX, -FLT_MAX, -FLT_MAX};
        int   li[5] = {0x7fffffff, 0x7fffffff, 0x7fffffff, 0x7fffffff, 0x7fffffff};
        for (int q = lane; q < C; q += 32) tk_insert(cval[q], cidx[q], lv, li);

        float tv[TOPK]; int ti[TOPK];
        int ptr = 0;
        #pragma unroll
        for (int r = 0; r < TOPK; r++) {
            float bv = (ptr < 5) ? lv[ptr] : -FLT_MAX;
            int   bi = (ptr < 5) ? li[ptr] : 0x7fffffff;
            #pragma unroll
            for (int s = 16; s > 0; s >>= 1) {
                float ov = __shfl_xor_sync(0xffffffffu, bv, s);
                int   oi = __shfl_xor_sync(0xffffffffu, bi, s);
                if (ov > bv || (ov == bv && oi < bi)) { bv = ov; bi = oi; }
            }
            if (ptr < 5 && li[ptr] == bi && lv[ptr] == bv) ptr++;
            tv[r] = bv; ti[r] = bi;
        }
        if (lane == 0) {
            float mm = tv[0];
            float e0 = expf(tv[0] - mm), e1 = expf(tv[1] - mm), e2 = expf(tv[2] - mm);
            float e3 = expf(tv[3] - mm), e4 = expf(tv[4] - mm);
            float inv5 = 1.0f / (e0 + e1 + e2 + e3 + e4);
            wsh[0]=e0*inv5; wsh[1]=e1*inv5; wsh[2]=e2*inv5; wsh[3]=e3*inv5; wsh[4]=e4*inv5;
            ids[0]=ti[0]; ids[1]=ti[1]; ids[2]=ti[2]; ids[3]=ti[3]; ids[4]=ti[4];
        }
    }
    __syncthreads();

    // ---- weighted embed gather ---------------------------------------------
    const float* e0 = emb + (size_t)ids[0] * D;
    const float* e1 = emb + (size_t)ids[1] * D;
    const float* e2 = emb + (size_t)ids[2] * D;
    const float* e3 = emb + (size_t)ids[3] * D;
    const float* e4 = emb + (size_t)ids[4] * D;
    float w0s = wsh[0], w1s = wsh[1], w2s = wsh[2], w3s = wsh[3], w4s = wsh[4];
    float* srow = sce + (size_t)row * D;
    #pragma unroll
    for (int d = t; d < D; d += 256) {
        srow[d] = w0s*__ldg(e0+d) + w1s*__ldg(e1+d) + w2s*__ldg(e2+d)
                + w3s*__ldg(e3+d) + w4s*__ldg(e4+d);
    }
}

// ---------------------------------------------------------------------------
// Kernel 2: attention  (block = (qtile of 4, b)), 256 threads, coalesced
// ---------------------------------------------------------------------------
__global__ __launch_bounds__(256, 4)
void attn_kernel(const float* __restrict__ qin,     // [BS, AT, D]
                 const float* __restrict__ sce,     // [BS, CAP, D]
                 const int*   __restrict__ clen,    // [BS]
                 float*       __restrict__ att) {   // [BS, AT, D]
    const int b  = blockIdx.y;
    const int q0 = blockIdx.x * 4;
    const int t  = threadIdx.x;
    const int wid = t >> 5, lane = t & 31;

    __shared__ __align__(16) float qs[4 * D];
    __shared__ float sc[4][CAP];

    const float* qbase = qin + ((size_t)b * AT + q0) * D;
    for (int i = t; i < 4 * D; i += 256) qs[i] = qbase[i];
    __syncthreads();

    {
        const float4* qs4 = (const float4*)qs;
        #pragma unroll
        for (int kk = 0; kk < 8; kk++) {
            const int k = wid * 8 + kk;
            const float4* kr = (const float4*)(sce + ((size_t)b * CAP + k) * D);
            float acc0 = 0.f, acc1 = 0.f, acc2 = 0.f, acc3 = 0.f;
            #pragma unroll
            for (int j = 0; j < D / 128; j++) {
                float4 kv = kr[lane + 32 * j];
                float4 q0v = qs4[0 * (D/4) + lane + 32 * j];
                float4 q1v = qs4[1 * (D/4) + lane + 32 * j];
                float4 q2v = qs4[2 * (D/4) + lane + 32 * j];
                float4 q3v = qs4[3 * (D/4) + lane + 32 * j];
                acc0 += kv.x*q0v.x + kv.y*q0v.y + kv.z*q0v.z + kv.w*q0v.w;
                acc1 += kv.x*q1v.x + kv.y*q1v.y + kv.z*q1v.z + kv.w*q1v.w;
                acc2 += kv.x*q2v.x + kv.y*q2v.y + kv.z*q2v.z + kv.w*q2v.w;
                acc3 += kv.x*q3v.x + kv.y*q3v.y + kv.z*q3v.z + kv.w*q3v.w;
            }
            #pragma unroll
            for (int s = 16; s > 0; s >>= 1) {
                acc0 += __shfl_xor_sync(0xffffffffu, acc0, s);
                acc1 += __shfl_xor_sync(0xffffffffu, acc1, s);
                acc2 += __shfl_xor_sync(0xffffffffu, acc2, s);
                acc3 += __shfl_xor_sync(0xffffffffu, acc3, s);
            }
            if (lane == 0) {
                const float scale = rsqrtf((float)D);
                sc[0][k] = acc0 * scale;
                sc[1][k] = acc1 * scale;
                sc[2][k] = acc2 * scale;
                sc[3][k] = acc3 * scale;
            }
        }
    }
    __syncthreads();

    if (wid < 4) {
        const int cl = clen[b];
        float v0 = (lane      < cl) ? sc[wid][lane]      : -1e9f;
        float v1 = (lane + 32 < cl) ? sc[wid][lane + 32] : -1e9f;
        float m = fmaxf(v0, v1);
        #pragma unroll
        for (int s = 16; s > 0; s >>= 1) m = fmaxf(m, __shfl_xor_sync(0xffffffffu, m, s));
        float x0 = expf(v0 - m), x1 = expf(v1 - m);
        float sum = x0 + x1;
        #pragma unroll
        for (int s = 16; s > 0; s >>= 1) sum += __shfl_xor_sync(0xffffffffu, sum, s);
        float inv = 1.0f / sum;
        sc[wid][lane]      = x0 * inv;
        sc[wid][lane + 32] = x1 * inv;
    }
    __syncthreads();

    float acc[4][3] = {};
    const float* srow = sce + (size_t)b * CAP * D;
    #pragma unroll 4
    for (int k = 0; k < CAP; k++) {
        float r0 = __ldg(srow + (size_t)k * D + t);
        float r1 = __ldg(srow + (size_t)k * D + t + 256);
        float r2 = __ldg(srow + (size_t)k * D + t + 512);
        #pragma unroll
        for (int qi = 0; qi < 4; qi++) {
            float wk = sc[qi][k];
            acc[qi][0] += wk * r0;
            acc[qi][1] += wk * r1;
            acc[qi][2] += wk * r2;
        }
    }
    #pragma unroll
    for (int qi = 0; qi < 4; qi++) {
        float* orow = att + ((size_t)b * AT + q0 + qi) * D;
        orow[t]       = acc[qi][0];
        orow[t + 256] = acc[qi][1];
        orow[t + 512] = acc[qi][2];
    }
}

// ---------------------------------------------------------------------------
// Kernel 3: final variable-length scatter/select; 2 float4 per thread (MLP)
// ---------------------------------------------------------------------------
__global__ __launch_bounds__(256)
void assemble_kernel(const float* __restrict__ emb,
                     const int*   __restrict__ ids,     // [BS, SEQ]
                     const int*   __restrict__ olen,    // [BS]
                     const int*   __restrict__ tlen,    // [BS]
                     const float* __restrict__ att,     // [BS, AT, D]
                     float4*      __restrict__ out) {
    const int i = blockIdx.x * 256 + threadIdx.x;     // over BS*SEQ*(D/8)
    const int total = BS * SEQ * (D / 8);
    if (i >= total) return;
    const int q  = i % (D / 8);                        // pair index within row
    const int bs = i / (D / 8);
    const int s  = bs & (SEQ - 1);
    const int b  = bs >> 8;

    const int rel = s - __ldg(olen + b);
    const int tl  = __ldg(tlen + b);
    const float4* src;
    if (rel >= 0 && rel < tl) {
        src = (const float4*)(att + ((size_t)b * AT + rel) * D);
    } else if (rel == tl) {
        src = (const float4*)(emb + (size_t)END_ID * D);
    } else {
        src = (const float4*)(emb + (size_t)__ldg(ids + bs) * D);
    }
    float4 a = src[2 * q];
    float4 c = src[2 * q + 1];
    float4* dst = out + (size_t)bs * (D / 4);
    dst[2 * q]     = a;
    dst[2 * q + 1] = c;
}

// ---------------------------------------------------------------------------
extern "C" void kernel_launch(void* const* d_in, const int* in_sizes, int n_in,
                              void* d_out, int out_size) {
    const float* caption_out      = (const float*)d_in[0];  // [BS,CAP,VOCAB]
    const float* embed_table      = (const float*)d_in[1];  // [VOCAB,D]
    const float* inputs_embeds_at = (const float*)d_in[2];  // [BS,AT,D]
    const int*   input_ids        = (const int*)  d_in[3];  // [BS,SEQ]
    const int*   origin_len       = (const int*)  d_in[4];  // [BS]
    const int*   target_len       = (const int*)  d_in[5];  // [BS]
    const int*   caption_len      = (const int*)  d_in[6];  // [BS]
    float4* out = (float4*)d_out;

    float* sce; cudaGetSymbolAddress((void**)&sce, g_sce);
    float* att; cudaGetSymbolAddress((void**)&att, g_att);

    topk_sce_kernel<<<BS * CAP, 256>>>(caption_out, embed_table, sce);

    dim3 g2(AT / 4, BS);
    attn_kernel<<<g2, 256>>>(inputs_embeds_at, sce, caption_len, att);

    const int total = BS * SEQ * (D / 8);
    assemble_kernel<<<(total + 255) / 256, 256>>>(embed_table, input_ids,
                                                  origin_len, target_len, att, out);
}